// round 12
// baseline (speedup 1.0000x reference)
#include <cuda_runtime.h>
#include <cuda_fp16.h>
#include <math.h>
#include <stdint.h>

// Problem dims
#define BATCH 1024
#define NB    512
#define HD    512
#define KP    576            // padded input dim (1+512 -> 576 = 9*64)
#define BNTOT (BATCH*NB)     // 524288

// ---------------------------------------------------------------------------
// Scratch (device globals)
// ---------------------------------------------------------------------------
__device__ __half g_Xh[BATCH*KP],  g_Xl[BATCH*KP];
__device__ __half g_W0T[HD*KP];      // W0^T padded [512 x 576], single fp16
__device__ __half g_W1T[HD*HD];
__device__ __half g_W2T[HD*HD];
__device__ __half g_WoT[HD*NB];      // Wout^T [512 x 512]
__device__ __half g_Lb [NB*NB];      // lambda_b rows
__device__ __half g_Ah[3*BNTOT],   g_Al[3*BNTOT];    // activations ping (hi/lo fp16)
__device__ __half g_Bh[3*BNTOT],   g_Bl[3*BNTOT];    // activations pong
__device__ __half g_SCh[2*BNTOT],  g_SCl[2*BNTOT];   // [sin ; cos] hi/lo
__device__ float g_P  [2*3*BNTOT];   // GEMM outputs (z-split: 2 segs; internal: 3 streams)
__device__ float g_SSp[2*2*BNTOT];   // conn GEMM partials (2 segs x 2 streams)

__device__ __forceinline__ void split2h(float x, __half* h, __half* l) {
    __half hi = __float2half_rn(x);
    *h = hi;
    *l = __float2half_rn(x - __half2float(hi));
}

__device__ __forceinline__ uint32_t smem_u32(const void* p) {
    uint32_t a;
    asm("{ .reg .u64 t; cvta.to.shared.u64 t, %1; cvt.u32.u64 %0, t; }" : "=r"(a) : "l"(p));
    return a;
}

__device__ __forceinline__ void mma_f16(float* d, const uint32_t* a, uint32_t b0, uint32_t b1) {
    asm volatile(
        "mma.sync.aligned.m16n8k16.row.col.f32.f16.f16.f32 "
        "{%0,%1,%2,%3},{%4,%5,%6,%7},{%8,%9},{%0,%1,%2,%3};"
        : "+f"(d[0]), "+f"(d[1]), "+f"(d[2]), "+f"(d[3])
        : "r"(a[0]), "r"(a[1]), "r"(a[2]), "r"(a[3]), "r"(b0), "r"(b1));
}

// 1-MUFU tanh (validated R9)
__device__ __forceinline__ float tanh_fast(float u) {
    float au = fabsf(u);
    float e = __expf(-2.f * au);
    float d = 1.f + e;
    float r = __fmaf_rn(-0.47058824f, d, 1.41176471f);  // 24/17 - 8/17*d
    r = r * (2.f - d * r);
    r = r * (2.f - d * r);
    r = r * (2.f - d * r);
    float t = (1.f - e) * r;
    return copysignf(t, u);
}

// ---- 4-wide vector helpers --------------------------------------------------
__device__ __forceinline__ void ld4(const float* p, float r[4]) {
    float4 a = *(const float4*)p;
    r[0]=a.x; r[1]=a.y; r[2]=a.z; r[3]=a.w;
}
__device__ __forceinline__ void acc4(const float* p, float r[4]) {
    float4 a = *(const float4*)p;
    r[0]+=a.x; r[1]+=a.y; r[2]+=a.z; r[3]+=a.w;
}
__device__ __forceinline__ void st4f(float* p, const float r[4]) {
    *(float4*)p = make_float4(r[0], r[1], r[2], r[3]);
}
__device__ __forceinline__ void split4h(const float r[4], __half* ph, __half* pl) {
    uint32_t h[2], l[2];
#pragma unroll
    for (int q = 0; q < 2; q++) {
        float x0 = r[2*q], x1 = r[2*q+1];
        __half2 hh = __floats2half2_rn(x0, x1);
        float f0 = __half2float(__low2half(hh)), f1 = __half2float(__high2half(hh));
        __half2 ll = __floats2half2_rn(x0 - f0, x1 - f1);
        h[q] = *(uint32_t*)&hh;
        l[q] = *(uint32_t*)&ll;
    }
    *(uint2*)ph = make_uint2(h[0], h[1]);
    *(uint2*)pl = make_uint2(l[0], l[1]);
}
__device__ __forceinline__ void ld4h2(const __half* ph, const __half* pl, float r[4]) {
    uint2 h = *(const uint2*)ph, l = *(const uint2*)pl;
    uint32_t hv[2] = {h.x, h.y};
    uint32_t lv[2] = {l.x, l.y};
#pragma unroll
    for (int q = 0; q < 2; q++) {
        __half2 hb = *(__half2*)&hv[q];
        __half2 lb = *(__half2*)&lv[q];
        r[2*q]   = __half2float(__low2half(hb))  + __half2float(__low2half(lb));
        r[2*q+1] = __half2float(__high2half(hb)) + __half2float(__high2half(lb));
    }
}

// ---------------------------------------------------------------------------
// HMMA 2-segment fp16 GEMM: C = (Ah + Al) * B^T, B single fp16 [N,K] row-major.
// internal2=1: one CTA accumulates BOTH segments (grid.z=1), writes final sum.
// internal2=0: blockIdx.z picks the segment, partial written at s*M*N.
// fuse_out!=nullptr (only with internal2): rows<1024 write value stream to
// fuse_out plus sin/cos hi/lo splits to g_SC*; other rows write C as usual.
// CTA tile 128(M) x 64(N), Kc=64, XOR-8 swizzle, 3-stage cp.async, 2 CTAs/SM.
// ---------------------------------------------------------------------------
#define STG_BYTES 24576
#define B_OFF     16384

__global__ void __launch_bounds__(256, 2)
hmma_gemm(const __half* __restrict__ Ah, const __half* __restrict__ Al,
          const __half* __restrict__ B,
          float* __restrict__ Cpart, int M, int N, int K,
          const float* __restrict__ bias, int bias_rows,
          int internal2, float* __restrict__ fuse_out)
{
    extern __shared__ __align__(1024) char smem[];
    const uint32_t sb = smem_u32(smem);
    const int tid = threadIdx.x;
    const int lane = tid & 31;
    const int wid = tid >> 5;
    const int wm = wid & 3;          // M direction (4 x 32 = 128)
    const int wn = wid >> 2;         // N direction (2 x 32 = 64)
    const int m0 = blockIdx.y * 128;
    const int n0 = blockIdx.x * 64;
    const int s  = internal2 ? 0 : blockIdx.z;
    const int ncK = K >> 6;
    const int TOT = internal2 ? 2 * ncK : ncK;

    const __half* __restrict__ Aseg0 = (s == 0) ? Ah : Al;
    float* __restrict__ C = Cpart + (size_t)s * M * N;
    const float* bp = (s == 0) ? bias : nullptr;

    float acc[2][4][4];
#pragma unroll
    for (int i = 0; i < 2; i++)
#pragma unroll
        for (int j = 0; j < 4; j++)
#pragma unroll
            for (int q = 0; q < 4; q++) acc[i][j][q] = 0.f;

    auto load_stage = [&](int c, int stg) {
        const __half* __restrict__ Ap = (c < ncK) ? Aseg0 : Al;
        const int kk = (c < ncK) ? c : c - ncK;
        const int kbase = kk << 6;
        const uint32_t abase = sb + stg * STG_BYTES;
        const uint32_t bbase = abase + B_OFF;
#pragma unroll
        for (int pass = 0; pass < 4; pass++) {       // A: 128 rows x 128B
            int idx = pass * 256 + tid;
            int row = idx >> 3, ch = idx & 7;
            uint32_t sa = abase + row * 128 + ((ch ^ (row & 7)) << 4);
            const void* ga = Ap + (size_t)(m0 + row) * K + kbase + ch * 8;
            asm volatile("cp.async.cg.shared.global [%0], [%1], 16;" :: "r"(sa), "l"(ga));
        }
#pragma unroll
        for (int pass = 0; pass < 2; pass++) {       // B: 64 rows x 128B
            int idx = pass * 256 + tid;
            int row = idx >> 3, ch = idx & 7;
            uint32_t sa = bbase + row * 128 + ((ch ^ (row & 7)) << 4);
            const void* ga = B + (size_t)(n0 + row) * K + kbase + ch * 8;
            asm volatile("cp.async.cg.shared.global [%0], [%1], 16;" :: "r"(sa), "l"(ga));
        }
    };

    load_stage(0, 0);
    asm volatile("cp.async.commit_group;" ::: "memory");
    load_stage(1, 1);
    asm volatile("cp.async.commit_group;" ::: "memory");

    int cbuf = 0, nbuf = 2;
    for (int c = 0; c < TOT; c++) {
        asm volatile("cp.async.wait_group 1;" ::: "memory");
        __syncthreads();
        if (c + 2 < TOT) load_stage(c + 2, nbuf);
        asm volatile("cp.async.commit_group;" ::: "memory");

        const uint32_t abase = sb + cbuf * STG_BYTES;
        const uint32_t bbase = abase + B_OFF;

#pragma unroll
        for (int kb = 0; kb < 4; kb++) {
            uint32_t a[2][4];
#pragma unroll
            for (int i = 0; i < 2; i++) {
                int row = wm * 32 + i * 16 + (lane & 15);
                int ch  = kb * 2 + (lane >> 4);
                uint32_t ad = abase + row * 128 + ((ch ^ (row & 7)) << 4);
                asm volatile("ldmatrix.sync.aligned.m8n8.x4.shared.b16 {%0,%1,%2,%3}, [%4];"
                             : "=r"(a[i][0]), "=r"(a[i][1]), "=r"(a[i][2]), "=r"(a[i][3])
                             : "r"(ad));
            }
#pragma unroll
            for (int j16 = 0; j16 < 2; j16++) {
                uint32_t b[4];
                int rn  = (lane & 7) + ((lane >> 4) << 3);
                int row = wn * 32 + j16 * 16 + rn;
                int ch  = kb * 2 + ((lane >> 3) & 1);
                uint32_t bd = bbase + row * 128 + ((ch ^ (row & 7)) << 4);
                asm volatile("ldmatrix.sync.aligned.m8n8.x4.shared.b16 {%0,%1,%2,%3}, [%4];"
                             : "=r"(b[0]), "=r"(b[1]), "=r"(b[2]), "=r"(b[3])
                             : "r"(bd));
#pragma unroll
                for (int i = 0; i < 2; i++) {
                    mma_f16(acc[i][2 * j16],     a[i], b[0], b[1]);
                    mma_f16(acc[i][2 * j16 + 1], a[i], b[2], b[3]);
                }
            }
        }
        cbuf = (cbuf == 2) ? 0 : cbuf + 1;
        nbuf = (nbuf == 2) ? 0 : nbuf + 1;
    }

    // epilogue
    const int gr  = lane >> 2;
    const int cp2 = (lane & 3) * 2;
#pragma unroll
    for (int i = 0; i < 2; i++) {
#pragma unroll
        for (int j8 = 0; j8 < 4; j8++) {
            int col = n0 + wn * 32 + j8 * 8 + cp2;
            int r0  = m0 + wm * 32 + i * 16 + gr;
            float bx = 0.f, by = 0.f;
            if (bp) { bx = bp[col]; by = bp[col + 1]; }
#pragma unroll
            for (int rr = 0; rr < 2; rr++) {
                int row = r0 + rr * 8;
                float2 v;
                v.x = acc[i][j8][2 * rr + 0];
                v.y = acc[i][j8][2 * rr + 1];
                if (bp && row < bias_rows) { v.x += bx; v.y += by; }
                if (fuse_out && row < BATCH) {
                    // value stream: write d_out stream 0 + sin/cos splits
                    size_t idx = (size_t)row * N + col;
                    *reinterpret_cast<float2*>(&fuse_out[idx]) = v;
                    float s0, c0, s1, c1;
                    __sincosf(v.x, &s0, &c0);
                    __sincosf(v.y, &s1, &c1);
                    __half2 sh = __floats2half2_rn(s0, s1);
                    __half2 sl = __floats2half2_rn(s0 - __half2float(__low2half(sh)),
                                                   s1 - __half2float(__high2half(sh)));
                    __half2 chh = __floats2half2_rn(c0, c1);
                    __half2 cl = __floats2half2_rn(c0 - __half2float(__low2half(chh)),
                                                   c1 - __half2float(__high2half(chh)));
                    *reinterpret_cast<__half2*>(&g_SCh[idx]) = sh;
                    *reinterpret_cast<__half2*>(&g_SCl[idx]) = sl;
                    *reinterpret_cast<__half2*>(&g_SCh[BNTOT + idx]) = chh;
                    *reinterpret_cast<__half2*>(&g_SCl[BNTOT + idx]) = cl;
                } else {
                    *reinterpret_cast<float2*>(&C[(size_t)row * N + col]) = v;
                }
            }
        }
    }
}

// ---------------------------------------------------------------------------
// Fused prep
// ---------------------------------------------------------------------------
__global__ void prep_all(const float* __restrict__ W0, const float* __restrict__ W1,
                         const float* __restrict__ W2, const float* __restrict__ Wo,
                         const float* __restrict__ lb)
{
    const int tx = threadIdx.x, ty = threadIdx.y;
    const int kb = blockIdx.x * 32, nb = blockIdx.y * 32;
    const int z = blockIdx.z;

    if (z == 4) {
        if (kb >= NB) return;
#pragma unroll
        for (int i = 0; i < 32; i += 8) {
            size_t o = (size_t)(nb + ty + i) * NB + kb + tx;
            g_Lb[o] = __float2half_rn(lb[o]);
        }
        return;
    }

    const float* W; __half* oh; int Kin, Kout;
    if (z == 0)      { W = W0; oh = g_W0T; Kin = NB + 1; Kout = KP; }
    else if (z == 1) { W = W1; oh = g_W1T; Kin = HD;     Kout = HD; }
    else if (z == 2) { W = W2; oh = g_W2T; Kin = HD;     Kout = HD; }
    else             { W = Wo; oh = g_WoT; Kin = HD;     Kout = HD; }
    if (kb >= Kout) return;

    __shared__ float tile[32][33];
#pragma unroll
    for (int i = 0; i < 32; i += 8) {
        int k = kb + ty + i;
        tile[ty + i][tx] = (k < Kin) ? W[(size_t)k * HD + nb + tx] : 0.f;
    }
    __syncthreads();
#pragma unroll
    for (int i = 0; i < 32; i += 8) {
        int n = nb + ty + i;
        size_t o = (size_t)n * Kout + kb + tx;
        oh[o] = __float2half_rn(tile[tx][ty + i]);
    }
}

// ---------------------------------------------------------------------------
// Elementwise kernels (4 elements per thread, grid 512)
// ---------------------------------------------------------------------------
__global__ void build_x_kernel(const float* __restrict__ t, const float* __restrict__ p,
                               const float* __restrict__ pl, const float* __restrict__ pu)
{
    int idx = blockIdx.x * blockDim.x + threadIdx.x;
    if (idx >= BATCH * KP) return;
    int row = idx / KP, col = idx - row * KP;
    float v;
    if (col == 0) v = 0.2f * t[row] - 1.0f;
    else if (col <= NB) {
        int j = col - 1;
        float lo = pl[j], hi = pu[j];
        v = (hi == lo) ? 0.f : (__fdividef(2.f * (p[row * NB + j] - lo), hi - lo) - 1.f);
    } else v = 0.f;
    split2h(v, &g_Xh[idx], &g_Xl[idx]);
}

// layer0 (z-split): 2 partials at {0,1}*BNTOT
__global__ void act0_kernel(const float* __restrict__ W0)
{
    int i = (blockIdx.x * blockDim.x + threadIdx.x) * 4;
    if (i >= BNTOT) return;
    int col = i & (HD - 1);
    float u[4], w0[4];
    ld4(g_P + i, u); acc4(g_P + BNTOT + i, u);
    ld4(W0 + col, w0);                           // W0 row 0
    float a[4], d1[4], d2[4];
#pragma unroll
    for (int q = 0; q < 4; q++) {
        float av = tanh_fast(u[q]);
        float ssq = 1.f - av * av;
        float gth = 0.2f * w0[q];
        a[q]  = av;
        d1[q] = ssq * gth;
        d2[q] = -2.f * av * ssq * gth * gth;
    }
    split4h(a,  g_Ah + i,             g_Al + i);
    split4h(d1, g_Ah + BNTOT + i,     g_Al + BNTOT + i);
    split4h(d2, g_Ah + 2 * BNTOT + i, g_Al + 2 * BNTOT + i);
}

// layers 1/2 (internal-accum GEMM): single copy, streams at t*BNTOT
__global__ void act12_kernel(__half* __restrict__ oh, __half* __restrict__ ol)
{
    int i = (blockIdx.x * blockDim.x + threadIdx.x) * 4;
    if (i >= BNTOT) return;
    float u[4], v[4], w[4];
    ld4(g_P + i, u);
    ld4(g_P + BNTOT + i, v);
    ld4(g_P + 2 * BNTOT + i, w);
    float a[4], d1[4], d2[4];
#pragma unroll
    for (int q = 0; q < 4; q++) {
        float av = tanh_fast(u[q]);
        float ssq = 1.f - av * av;
        a[q]  = av;
        d1[q] = ssq * v[q];
        d2[q] = ssq * (w[q] - 2.f * av * v[q] * v[q]);
    }
    split4h(a,  oh + i,             ol + i);
    split4h(d1, oh + BNTOT + i,     ol + BNTOT + i);
    split4h(d2, oh + 2 * BNTOT + i, ol + 2 * BNTOT + i);
}

// combine streams 1,2 + conn partials + physics -> d_out (no MUFU)
__global__ void final_kernel(float* __restrict__ out, const float* __restrict__ lm,
                             const float* __restrict__ ld, const float* __restrict__ p)
{
    int i = (blockIdx.x * blockDim.x + threadIdx.x) * 4;
    if (i >= BNTOT) return;
    int col = i & (NB - 1);
    float ot[4], ott[4], ssS[4], ssC[4], pv[4], lmv[4], ldv[4], sv[4], cv[4];
    ld4(g_P + BNTOT + i, ot);
    ld4(g_P + 2 * BNTOT + i, ott);
    ld4(g_SSp + i, ssS);            acc4(g_SSp + 2 * BNTOT + i, ssS);
    ld4(g_SSp + BNTOT + i, ssC);    acc4(g_SSp + 3 * BNTOT + i, ssC);
    ld4h2(g_SCh + i,         g_SCl + i,         sv);
    ld4h2(g_SCh + BNTOT + i, g_SCl + BNTOT + i, cv);
    ld4(p + i, pv);
    ld4(lm + col, lmv);
    ld4(ld + col, ldv);
    float r1[4], r2[4];
#pragma unroll
    for (int q = 0; q < 4; q++) {
        float conn = sv[q] * ssC[q] - cv[q] * ssS[q];
        r1[q] = ot[q];
        r2[q] = lmv[q] * ott[q] + ldv[q] * ot[q] + conn - pv[q];
    }
    st4f(out + BNTOT + i, r1);
    st4f(out + 2 * BNTOT + i, r2);
}

// ---------------------------------------------------------------------------
// Launch
// ---------------------------------------------------------------------------
extern "C" void kernel_launch(void* const* d_in, const int* in_sizes, int n_in,
                              void* d_out, int out_size)
{
    const float* t    = (const float*)d_in[0];
    const float* p    = (const float*)d_in[1];
    const float* W0   = (const float*)d_in[2];
    const float* b0   = (const float*)d_in[3];
    const float* W1   = (const float*)d_in[4];
    const float* b1   = (const float*)d_in[5];
    const float* W2   = (const float*)d_in[6];
    const float* b2   = (const float*)d_in[7];
    const float* Wout = (const float*)d_in[8];
    const float* bout = (const float*)d_in[9];
    const float* lm   = (const float*)d_in[10];
    const float* ld   = (const float*)d_in[11];
    const float* lb   = (const float*)d_in[12];
    const float* pl   = (const float*)d_in[13];
    const float* pu   = (const float*)d_in[14];
    float* out = (float*)d_out;

    cudaFuncSetAttribute(hmma_gemm, cudaFuncAttributeMaxDynamicSharedMemorySize, 3 * STG_BYTES);
    const int GSM = 3 * STG_BYTES;

    __half *pXh,*pXl,*pW0,*pW1,*pW2,*pWo,*pLb,*pAh,*pAl,*pBh,*pBl,*pSCh,*pSCl;
    float *pP,*pSSp;
    cudaGetSymbolAddress((void**)&pXh, g_Xh);   cudaGetSymbolAddress((void**)&pXl, g_Xl);
    cudaGetSymbolAddress((void**)&pW0, g_W0T);
    cudaGetSymbolAddress((void**)&pW1, g_W1T);
    cudaGetSymbolAddress((void**)&pW2, g_W2T);
    cudaGetSymbolAddress((void**)&pWo, g_WoT);
    cudaGetSymbolAddress((void**)&pLb, g_Lb);
    cudaGetSymbolAddress((void**)&pAh, g_Ah);   cudaGetSymbolAddress((void**)&pAl, g_Al);
    cudaGetSymbolAddress((void**)&pBh, g_Bh);   cudaGetSymbolAddress((void**)&pBl, g_Bl);
    cudaGetSymbolAddress((void**)&pSCh, g_SCh); cudaGetSymbolAddress((void**)&pSCl, g_SCl);
    cudaGetSymbolAddress((void**)&pP, g_P);     cudaGetSymbolAddress((void**)&pSSp, g_SSp);

    const int EW = 256;
    const int VG4 = BNTOT / (EW * 4);   // 512 blocks for 4-wide kernels

    // prep
    build_x_kernel<<<(BATCH * KP + EW - 1) / EW, EW>>>(t, p, pl, pu);
    prep_all<<<dim3(KP / 32, HD / 32, 5), dim3(32, 8)>>>(W0, W1, W2, Wout, lb);

    // layer 0: z-split (grid 8x8x2), 2 partials
    hmma_gemm<<<dim3(HD / 64, BATCH / 128, 2), 256, GSM>>>(
        pXh, pXl, pW0, pP, BATCH, HD, KP, b0, BATCH, 0, nullptr);
    act0_kernel<<<VG4, EW>>>(W0);

    // layer 1: internal 2-seg accumulation (grid 8x24)
    hmma_gemm<<<dim3(HD / 64, 3 * BATCH / 128, 1), 256, GSM>>>(
        pAh, pAl, pW1, pP, 3 * BATCH, HD, HD, b1, BATCH, 1, nullptr);
    act12_kernel<<<VG4, EW>>>(pBh, pBl);

    // layer 2
    hmma_gemm<<<dim3(HD / 64, 3 * BATCH / 128, 1), 256, GSM>>>(
        pBh, pBl, pW2, pP, 3 * BATCH, HD, HD, b2, BATCH, 1, nullptr);
    act12_kernel<<<VG4, EW>>>(pAh, pAl);

    // output layer: internal accum + fused sincos epilogue.
    // rows<1024 -> d_out stream0 + sin/cos splits; rows>=1024 -> g_P streams 1,2
    hmma_gemm<<<dim3(NB / 64, 3 * BATCH / 128, 1), 256, GSM>>>(
        pAh, pAl, pWo, pP, 3 * BATCH, NB, HD, bout, BATCH, 1, out);

    // connectivity: z-split (grid 8x16x2) -> partials in g_SSp
    hmma_gemm<<<dim3(NB / 64, 2 * BATCH / 128, 2), 256, GSM>>>(
        pSCh, pSCl, pLb, pSSp, 2 * BATCH, NB, NB, nullptr, 0, 0, nullptr);

    // combine streams 1,2 + physics -> d_out
    final_kernel<<<VG4, EW>>>(out, lm, ld, p);
}

// round 14
// speedup vs baseline: 1.1224x; 1.1224x over previous
#include <cuda_runtime.h>
#include <cuda_fp16.h>
#include <math.h>
#include <stdint.h>

// Problem dims
#define BATCH 1024
#define NB    512
#define HD    512
#define KP    576            // padded input dim (1+512 -> 576 = 9*64)
#define BNTOT (BATCH*NB)     // 524288

// ---------------------------------------------------------------------------
// Scratch (device globals)
// ---------------------------------------------------------------------------
__device__ __half g_Xh[BATCH*KP],  g_Xl[BATCH*KP];
__device__ __half g_W0T[HD*KP];      // W0^T padded [512 x 576], single fp16
__device__ __half g_W1T[HD*HD];
__device__ __half g_W2T[HD*HD];
__device__ __half g_WoT[HD*NB];      // Wout^T [512 x 512]
__device__ __half g_Lb [NB*NB];      // lambda_b rows
__device__ __half g_Ah[3*BNTOT],   g_Al[3*BNTOT];    // activations ping (hi/lo fp16)
__device__ __half g_Bh[3*BNTOT],   g_Bl[3*BNTOT];    // activations pong
__device__ __half g_SCh[2*BNTOT],  g_SCl[2*BNTOT];   // [sin ; cos] hi/lo
__device__ float g_P  [2*3*BNTOT];   // GEMM partials: segment s at offset s*M*N
__device__ float g_SSp[2*2*BNTOT];   // conn GEMM partials

__device__ __forceinline__ void split2h(float x, __half* h, __half* l) {
    __half hi = __float2half_rn(x);
    *h = hi;
    *l = __float2half_rn(x - __half2float(hi));
}

__device__ __forceinline__ uint32_t smem_u32(const void* p) {
    uint32_t a;
    asm("{ .reg .u64 t; cvta.to.shared.u64 t, %1; cvt.u32.u64 %0, t; }" : "=r"(a) : "l"(p));
    return a;
}

// fp32-accumulate HMMA
__device__ __forceinline__ void mma_f32(float* d, const uint32_t* a, uint32_t b0, uint32_t b1) {
    asm volatile(
        "mma.sync.aligned.m16n8k16.row.col.f32.f16.f16.f32 "
        "{%0,%1,%2,%3},{%4,%5,%6,%7},{%8,%9},{%0,%1,%2,%3};"
        : "+f"(d[0]), "+f"(d[1]), "+f"(d[2]), "+f"(d[3])
        : "r"(a[0]), "r"(a[1]), "r"(a[2]), "r"(a[3]), "r"(b0), "r"(b1));
}
// fp16-accumulate HMMA (2x rate) — used for the lo segment only
__device__ __forceinline__ void mma_acc16(uint32_t* d, const uint32_t* a, uint32_t b0, uint32_t b1) {
    asm volatile(
        "mma.sync.aligned.m16n8k16.row.col.f16.f16.f16.f16 "
        "{%0,%1},{%2,%3,%4,%5},{%6,%7},{%0,%1};"
        : "+r"(d[0]), "+r"(d[1])
        : "r"(a[0]), "r"(a[1]), "r"(a[2]), "r"(a[3]), "r"(b0), "r"(b1));
}

// 1-MUFU tanh (validated R9)
__device__ __forceinline__ float tanh_fast(float u) {
    float au = fabsf(u);
    float e = __expf(-2.f * au);
    float d = 1.f + e;
    float r = __fmaf_rn(-0.47058824f, d, 1.41176471f);  // 24/17 - 8/17*d
    r = r * (2.f - d * r);
    r = r * (2.f - d * r);
    r = r * (2.f - d * r);
    float t = (1.f - e) * r;
    return copysignf(t, u);
}

// ---- 4-wide vector helpers --------------------------------------------------
__device__ __forceinline__ void ld4(const float* p, float r[4]) {
    float4 a = *(const float4*)p;
    r[0]=a.x; r[1]=a.y; r[2]=a.z; r[3]=a.w;
}
__device__ __forceinline__ void acc4(const float* p, float r[4]) {
    float4 a = *(const float4*)p;
    r[0]+=a.x; r[1]+=a.y; r[2]+=a.z; r[3]+=a.w;
}
__device__ __forceinline__ void st4f(float* p, const float r[4]) {
    *(float4*)p = make_float4(r[0], r[1], r[2], r[3]);
}
__device__ __forceinline__ void split4h(const float r[4], __half* ph, __half* pl) {
    uint32_t h[2], l[2];
#pragma unroll
    for (int q = 0; q < 2; q++) {
        float x0 = r[2*q], x1 = r[2*q+1];
        __half2 hh = __floats2half2_rn(x0, x1);
        float f0 = __half2float(__low2half(hh)), f1 = __half2float(__high2half(hh));
        __half2 ll = __floats2half2_rn(x0 - f0, x1 - f1);
        h[q] = *(uint32_t*)&hh;
        l[q] = *(uint32_t*)&ll;
    }
    *(uint2*)ph = make_uint2(h[0], h[1]);
    *(uint2*)pl = make_uint2(l[0], l[1]);
}
__device__ __forceinline__ void ld4h2(const __half* ph, const __half* pl, float r[4]) {
    uint2 h = *(const uint2*)ph, l = *(const uint2*)pl;
    uint32_t hv[2] = {h.x, h.y};
    uint32_t lv[2] = {l.x, l.y};
#pragma unroll
    for (int q = 0; q < 2; q++) {
        __half2 hb = *(__half2*)&hv[q];
        __half2 lb = *(__half2*)&lv[q];
        r[2*q]   = __half2float(__low2half(hb))  + __half2float(__low2half(lb));
        r[2*q+1] = __half2float(__high2half(hb)) + __half2float(__high2half(lb));
    }
}

// ---------------------------------------------------------------------------
// HMMA 2-segment fp16 GEMM (z-split): C_s = A_s * B^T, partial at s*M*N.
// s=0: Ah, fp32 accum, +bias.  s=1: Al, fp16 accum (2x tensor rate), no bias.
// CTA tile 128(M) x 64(N), Kc=64, XOR-8 swizzle, 3-stage cp.async, 2 CTAs/SM.
// ---------------------------------------------------------------------------
#define STG_BYTES 24576
#define B_OFF     16384

__global__ void __launch_bounds__(256, 2)
hmma_gemm(const __half* __restrict__ Ah, const __half* __restrict__ Al,
          const __half* __restrict__ B,
          float* __restrict__ Cpart, int M, int N, int K,
          const float* __restrict__ bias, int bias_rows)
{
    extern __shared__ __align__(1024) char smem[];
    const uint32_t sb = smem_u32(smem);
    const int tid = threadIdx.x;
    const int lane = tid & 31;
    const int wid = tid >> 5;
    const int wm = wid & 3;          // M direction (4 x 32 = 128)
    const int wn = wid >> 2;         // N direction (2 x 32 = 64)
    const int m0 = blockIdx.y * 128;
    const int n0 = blockIdx.x * 64;
    const int s  = blockIdx.z;
    const int ncK = K >> 6;

    const __half* __restrict__ Ap = (s == 0) ? Ah : Al;
    float* __restrict__ C = Cpart + (size_t)s * M * N;
    const float* bp = (s == 0) ? bias : nullptr;

    auto load_stage = [&](int kk, int stg) {
        const int kbase = kk << 6;
        const uint32_t abase = sb + stg * STG_BYTES;
        const uint32_t bbase = abase + B_OFF;
#pragma unroll
        for (int pass = 0; pass < 4; pass++) {       // A: 128 rows x 128B
            int idx = pass * 256 + tid;
            int row = idx >> 3, ch = idx & 7;
            uint32_t sa = abase + row * 128 + ((ch ^ (row & 7)) << 4);
            const void* ga = Ap + (size_t)(m0 + row) * K + kbase + ch * 8;
            asm volatile("cp.async.cg.shared.global [%0], [%1], 16;" :: "r"(sa), "l"(ga));
        }
#pragma unroll
        for (int pass = 0; pass < 2; pass++) {       // B: 64 rows x 128B
            int idx = pass * 256 + tid;
            int row = idx >> 3, ch = idx & 7;
            uint32_t sa = bbase + row * 128 + ((ch ^ (row & 7)) << 4);
            const void* ga = B + (size_t)(n0 + row) * K + kbase + ch * 8;
            asm volatile("cp.async.cg.shared.global [%0], [%1], 16;" :: "r"(sa), "l"(ga));
        }
    };

    load_stage(0, 0);
    asm volatile("cp.async.commit_group;" ::: "memory");
    load_stage(1, 1);
    asm volatile("cp.async.commit_group;" ::: "memory");

    const int gr  = lane >> 2;
    const int cp2 = (lane & 3) * 2;

    if (s == 0) {
        // ---------- fp32-accumulate path (hi segment) ----------
        float acc[2][4][4];
#pragma unroll
        for (int i = 0; i < 2; i++)
#pragma unroll
            for (int j = 0; j < 4; j++)
#pragma unroll
                for (int q = 0; q < 4; q++) acc[i][j][q] = 0.f;

        int cbuf = 0, nbuf = 2;
        for (int c = 0; c < ncK; c++) {
            asm volatile("cp.async.wait_group 1;" ::: "memory");
            __syncthreads();
            if (c + 2 < ncK) load_stage(c + 2, nbuf);
            asm volatile("cp.async.commit_group;" ::: "memory");

            const uint32_t abase = sb + cbuf * STG_BYTES;
            const uint32_t bbase = abase + B_OFF;
#pragma unroll
            for (int kb = 0; kb < 4; kb++) {
                uint32_t a[2][4];
#pragma unroll
                for (int i = 0; i < 2; i++) {
                    int row = wm * 32 + i * 16 + (lane & 15);
                    int ch  = kb * 2 + (lane >> 4);
                    uint32_t ad = abase + row * 128 + ((ch ^ (row & 7)) << 4);
                    asm volatile("ldmatrix.sync.aligned.m8n8.x4.shared.b16 {%0,%1,%2,%3}, [%4];"
                                 : "=r"(a[i][0]), "=r"(a[i][1]), "=r"(a[i][2]), "=r"(a[i][3])
                                 : "r"(ad));
                }
#pragma unroll
                for (int j16 = 0; j16 < 2; j16++) {
                    uint32_t b[4];
                    int rn  = (lane & 7) + ((lane >> 4) << 3);
                    int row = wn * 32 + j16 * 16 + rn;
                    int ch  = kb * 2 + ((lane >> 3) & 1);
                    uint32_t bd = bbase + row * 128 + ((ch ^ (row & 7)) << 4);
                    asm volatile("ldmatrix.sync.aligned.m8n8.x4.shared.b16 {%0,%1,%2,%3}, [%4];"
                                 : "=r"(b[0]), "=r"(b[1]), "=r"(b[2]), "=r"(b[3])
                                 : "r"(bd));
#pragma unroll
                    for (int i = 0; i < 2; i++) {
                        mma_f32(acc[i][2 * j16],     a[i], b[0], b[1]);
                        mma_f32(acc[i][2 * j16 + 1], a[i], b[2], b[3]);
                    }
                }
            }
            cbuf = (cbuf == 2) ? 0 : cbuf + 1;
            nbuf = (nbuf == 2) ? 0 : nbuf + 1;
        }
#pragma unroll
        for (int i = 0; i < 2; i++) {
#pragma unroll
            for (int j8 = 0; j8 < 4; j8++) {
                int col = n0 + wn * 32 + j8 * 8 + cp2;
                int r0  = m0 + wm * 32 + i * 16 + gr;
                float bx = 0.f, by = 0.f;
                if (bp) { bx = bp[col]; by = bp[col + 1]; }
#pragma unroll
                for (int rr = 0; rr < 2; rr++) {
                    int row = r0 + rr * 8;
                    float2 v;
                    v.x = acc[i][j8][2 * rr + 0];
                    v.y = acc[i][j8][2 * rr + 1];
                    if (bp && row < bias_rows) { v.x += bx; v.y += by; }
                    *reinterpret_cast<float2*>(&C[(size_t)row * N + col]) = v;
                }
            }
        }
    } else {
        // ---------- fp16-accumulate path (lo segment, 2x rate) ----------
        uint32_t acch[2][4][2];
#pragma unroll
        for (int i = 0; i < 2; i++)
#pragma unroll
            for (int j = 0; j < 4; j++) { acch[i][j][0] = 0u; acch[i][j][1] = 0u; }

        int cbuf = 0, nbuf = 2;
        for (int c = 0; c < ncK; c++) {
            asm volatile("cp.async.wait_group 1;" ::: "memory");
            __syncthreads();
            if (c + 2 < ncK) load_stage(c + 2, nbuf);
            asm volatile("cp.async.commit_group;" ::: "memory");

            const uint32_t abase = sb + cbuf * STG_BYTES;
            const uint32_t bbase = abase + B_OFF;
#pragma unroll
            for (int kb = 0; kb < 4; kb++) {
                uint32_t a[2][4];
#pragma unroll
                for (int i = 0; i < 2; i++) {
                    int row = wm * 32 + i * 16 + (lane & 15);
                    int ch  = kb * 2 + (lane >> 4);
                    uint32_t ad = abase + row * 128 + ((ch ^ (row & 7)) << 4);
                    asm volatile("ldmatrix.sync.aligned.m8n8.x4.shared.b16 {%0,%1,%2,%3}, [%4];"
                                 : "=r"(a[i][0]), "=r"(a[i][1]), "=r"(a[i][2]), "=r"(a[i][3])
                                 : "r"(ad));
                }
#pragma unroll
                for (int j16 = 0; j16 < 2; j16++) {
                    uint32_t b[4];
                    int rn  = (lane & 7) + ((lane >> 4) << 3);
                    int row = wn * 32 + j16 * 16 + rn;
                    int ch  = kb * 2 + ((lane >> 3) & 1);
                    uint32_t bd = bbase + row * 128 + ((ch ^ (row & 7)) << 4);
                    asm volatile("ldmatrix.sync.aligned.m8n8.x4.shared.b16 {%0,%1,%2,%3}, [%4];"
                                 : "=r"(b[0]), "=r"(b[1]), "=r"(b[2]), "=r"(b[3])
                                 : "r"(bd));
#pragma unroll
                    for (int i = 0; i < 2; i++) {
                        mma_acc16(acch[i][2 * j16],     a[i], b[0], b[1]);
                        mma_acc16(acch[i][2 * j16 + 1], a[i], b[2], b[3]);
                    }
                }
            }
            cbuf = (cbuf == 2) ? 0 : cbuf + 1;
            nbuf = (nbuf == 2) ? 0 : nbuf + 1;
        }
#pragma unroll
        for (int i = 0; i < 2; i++) {
#pragma unroll
            for (int j8 = 0; j8 < 4; j8++) {
                int col = n0 + wn * 32 + j8 * 8 + cp2;
                int r0  = m0 + wm * 32 + i * 16 + gr;
#pragma unroll
                for (int rr = 0; rr < 2; rr++) {
                    int row = r0 + rr * 8;
                    __half2 hv = *reinterpret_cast<__half2*>(&acch[i][j8][rr]);
                    float2 v = __half22float2(hv);
                    *reinterpret_cast<float2*>(&C[(size_t)row * N + col]) = v;
                }
            }
        }
    }
}

// ---------------------------------------------------------------------------
// Fused prep
// ---------------------------------------------------------------------------
__global__ void prep_all(const float* __restrict__ W0, const float* __restrict__ W1,
                         const float* __restrict__ W2, const float* __restrict__ Wo,
                         const float* __restrict__ lb)
{
    const int tx = threadIdx.x, ty = threadIdx.y;
    const int kb = blockIdx.x * 32, nb = blockIdx.y * 32;
    const int z = blockIdx.z;

    if (z == 4) {
        if (kb >= NB) return;
#pragma unroll
        for (int i = 0; i < 32; i += 8) {
            size_t o = (size_t)(nb + ty + i) * NB + kb + tx;
            g_Lb[o] = __float2half_rn(lb[o]);
        }
        return;
    }

    const float* W; __half* oh; int Kin, Kout;
    if (z == 0)      { W = W0; oh = g_W0T; Kin = NB + 1; Kout = KP; }
    else if (z == 1) { W = W1; oh = g_W1T; Kin = HD;     Kout = HD; }
    else if (z == 2) { W = W2; oh = g_W2T; Kin = HD;     Kout = HD; }
    else             { W = Wo; oh = g_WoT; Kin = HD;     Kout = HD; }
    if (kb >= Kout) return;

    __shared__ float tile[32][33];
#pragma unroll
    for (int i = 0; i < 32; i += 8) {
        int k = kb + ty + i;
        tile[ty + i][tx] = (k < Kin) ? W[(size_t)k * HD + nb + tx] : 0.f;
    }
    __syncthreads();
#pragma unroll
    for (int i = 0; i < 32; i += 8) {
        int n = nb + ty + i;
        size_t o = (size_t)n * Kout + kb + tx;
        oh[o] = __float2half_rn(tile[tx][ty + i]);
    }
}

// ---------------------------------------------------------------------------
// Elementwise kernels (4 elements per thread, grid 512)
// ---------------------------------------------------------------------------
__global__ void build_x_kernel(const float* __restrict__ t, const float* __restrict__ p,
                               const float* __restrict__ pl, const float* __restrict__ pu)
{
    int idx = blockIdx.x * blockDim.x + threadIdx.x;
    if (idx >= BATCH * KP) return;
    int row = idx / KP, col = idx - row * KP;
    float v;
    if (col == 0) v = 0.2f * t[row] - 1.0f;
    else if (col <= NB) {
        int j = col - 1;
        float lo = pl[j], hi = pu[j];
        v = (hi == lo) ? 0.f : (__fdividef(2.f * (p[row * NB + j] - lo), hi - lo) - 1.f);
    } else v = 0.f;
    split2h(v, &g_Xh[idx], &g_Xl[idx]);
}

// layer0 (z-split M=1024): 2 partials at {0,1}*BNTOT
__global__ void act0_kernel(const float* __restrict__ W0)
{
    int i = (blockIdx.x * blockDim.x + threadIdx.x) * 4;
    if (i >= BNTOT) return;
    int col = i & (HD - 1);
    float u[4], w0[4];
    ld4(g_P + i, u); acc4(g_P + BNTOT + i, u);
    ld4(W0 + col, w0);                           // W0 row 0
    float a[4], d1[4], d2[4];
#pragma unroll
    for (int q = 0; q < 4; q++) {
        float av = tanh_fast(u[q]);
        float ssq = 1.f - av * av;
        float gth = 0.2f * w0[q];
        a[q]  = av;
        d1[q] = ssq * gth;
        d2[q] = -2.f * av * ssq * gth * gth;
    }
    split4h(a,  g_Ah + i,             g_Al + i);
    split4h(d1, g_Ah + BNTOT + i,     g_Al + BNTOT + i);
    split4h(d2, g_Ah + 2 * BNTOT + i, g_Al + 2 * BNTOT + i);
}

// layers 1/2 (z-split M=3072): segment stride 3*BNTOT; stream t at t*BNTOT
__global__ void act12_kernel(__half* __restrict__ oh, __half* __restrict__ ol)
{
    int i = (blockIdx.x * blockDim.x + threadIdx.x) * 4;
    if (i >= BNTOT) return;
    float u[4], v[4], w[4];
    ld4(g_P + i, u);              acc4(g_P + 3 * BNTOT + i, u);
    ld4(g_P + BNTOT + i, v);      acc4(g_P + 4 * BNTOT + i, v);
    ld4(g_P + 2 * BNTOT + i, w);  acc4(g_P + 5 * BNTOT + i, w);
    float a[4], d1[4], d2[4];
#pragma unroll
    for (int q = 0; q < 4; q++) {
        float av = tanh_fast(u[q]);
        float ssq = 1.f - av * av;
        a[q]  = av;
        d1[q] = ssq * v[q];
        d2[q] = ssq * (w[q] - 2.f * av * v[q] * v[q]);
    }
    split4h(a,  oh + i,             ol + i);
    split4h(d1, oh + BNTOT + i,     ol + BNTOT + i);
    split4h(d2, oh + 2 * BNTOT + i, ol + 2 * BNTOT + i);
}

// combine out value stream -> d_out stream 0, emit sin/cos hi/lo
__global__ void sincos_kernel(float* __restrict__ out)
{
    int i = (blockIdx.x * blockDim.x + threadIdx.x) * 4;
    if (i >= BNTOT) return;
    float o[4];
    ld4(g_P + i, o); acc4(g_P + 3 * BNTOT + i, o);
    st4f(out + i, o);
    float sv[4], cv[4];
#pragma unroll
    for (int q = 0; q < 4; q++) __sincosf(o[q], &sv[q], &cv[q]);
    split4h(sv, g_SCh + i,         g_SCl + i);
    split4h(cv, g_SCh + BNTOT + i, g_SCl + BNTOT + i);
}

// combine streams 1,2 + conn partials + physics -> d_out (no MUFU)
__global__ void final_kernel(float* __restrict__ out, const float* __restrict__ lm,
                             const float* __restrict__ ld, const float* __restrict__ p)
{
    int i = (blockIdx.x * blockDim.x + threadIdx.x) * 4;
    if (i >= BNTOT) return;
    int col = i & (NB - 1);
    float ot[4], ott[4], ssS[4], ssC[4], pv[4], lmv[4], ldv[4], sv[4], cv[4];
    ld4(g_P + BNTOT + i, ot);       acc4(g_P + 4 * BNTOT + i, ot);
    ld4(g_P + 2 * BNTOT + i, ott);  acc4(g_P + 5 * BNTOT + i, ott);
    ld4(g_SSp + i, ssS);            acc4(g_SSp + 2 * BNTOT + i, ssS);
    ld4(g_SSp + BNTOT + i, ssC);    acc4(g_SSp + 3 * BNTOT + i, ssC);
    ld4h2(g_SCh + i,         g_SCl + i,         sv);
    ld4h2(g_SCh + BNTOT + i, g_SCl + BNTOT + i, cv);
    ld4(p + i, pv);
    ld4(lm + col, lmv);
    ld4(ld + col, ldv);
    float r1[4], r2[4];
#pragma unroll
    for (int q = 0; q < 4; q++) {
        float conn = sv[q] * ssC[q] - cv[q] * ssS[q];
        r1[q] = ot[q];
        r2[q] = lmv[q] * ott[q] + ldv[q] * ot[q] + conn - pv[q];
    }
    st4f(out + BNTOT + i, r1);
    st4f(out + 2 * BNTOT + i, r2);
}

// ---------------------------------------------------------------------------
// Launch
// ---------------------------------------------------------------------------
extern "C" void kernel_launch(void* const* d_in, const int* in_sizes, int n_in,
                              void* d_out, int out_size)
{
    const float* t    = (const float*)d_in[0];
    const float* p    = (const float*)d_in[1];
    const float* W0   = (const float*)d_in[2];
    const float* b0   = (const float*)d_in[3];
    const float* W1   = (const float*)d_in[4];
    const float* b1   = (const float*)d_in[5];
    const float* W2   = (const float*)d_in[6];
    const float* b2   = (const float*)d_in[7];
    const float* Wout = (const float*)d_in[8];
    const float* bout = (const float*)d_in[9];
    const float* lm   = (const float*)d_in[10];
    const float* ld   = (const float*)d_in[11];
    const float* lb   = (const float*)d_in[12];
    const float* pl   = (const float*)d_in[13];
    const float* pu   = (const float*)d_in[14];
    float* out = (float*)d_out;

    cudaFuncSetAttribute(hmma_gemm, cudaFuncAttributeMaxDynamicSharedMemorySize, 3 * STG_BYTES);
    const int GSM = 3 * STG_BYTES;

    __half *pXh,*pXl,*pW0,*pW1,*pW2,*pWo,*pLb,*pAh,*pAl,*pBh,*pBl,*pSCh,*pSCl;
    float *pP,*pSSp;
    cudaGetSymbolAddress((void**)&pXh, g_Xh);   cudaGetSymbolAddress((void**)&pXl, g_Xl);
    cudaGetSymbolAddress((void**)&pW0, g_W0T);
    cudaGetSymbolAddress((void**)&pW1, g_W1T);
    cudaGetSymbolAddress((void**)&pW2, g_W2T);
    cudaGetSymbolAddress((void**)&pWo, g_WoT);
    cudaGetSymbolAddress((void**)&pLb, g_Lb);
    cudaGetSymbolAddress((void**)&pAh, g_Ah);   cudaGetSymbolAddress((void**)&pAl, g_Al);
    cudaGetSymbolAddress((void**)&pBh, g_Bh);   cudaGetSymbolAddress((void**)&pBl, g_Bl);
    cudaGetSymbolAddress((void**)&pSCh, g_SCh); cudaGetSymbolAddress((void**)&pSCl, g_SCl);
    cudaGetSymbolAddress((void**)&pP, g_P);     cudaGetSymbolAddress((void**)&pSSp, g_SSp);

    const int EW = 256;
    const int VG4 = BNTOT / (EW * 4);   // 512 blocks for 4-wide kernels

    // prep
    build_x_kernel<<<(BATCH * KP + EW - 1) / EW, EW>>>(t, p, pl, pu);
    prep_all<<<dim3(KP / 32, HD / 32, 5), dim3(32, 8)>>>(W0, W1, W2, Wout, lb);

    // layer 0: [1024,576] x [512,576]^T + b0  (2 segment partials)
    hmma_gemm<<<dim3(HD / 64, BATCH / 128, 2), 256, GSM>>>(pXh, pXl, pW0, pP, BATCH, HD, KP, b0, BATCH);
    act0_kernel<<<VG4, EW>>>(W0);

    // layer 1: [3072,512] x W1^T
    hmma_gemm<<<dim3(HD / 64, 3 * BATCH / 128, 2), 256, GSM>>>(pAh, pAl, pW1, pP, 3 * BATCH, HD, HD, b1, BATCH);
    act12_kernel<<<VG4, EW>>>(pBh, pBl);

    // layer 2
    hmma_gemm<<<dim3(HD / 64, 3 * BATCH / 128, 2), 256, GSM>>>(pBh, pBl, pW2, pP, 3 * BATCH, HD, HD, b2, BATCH);
    act12_kernel<<<VG4, EW>>>(pAh, pAl);

    // output layer -> partials in g_P
    hmma_gemm<<<dim3(NB / 64, 3 * BATCH / 128, 2), 256, GSM>>>(pAh, pAl, pWo, pP, 3 * BATCH, NB, HD, bout, BATCH);

    // combine value stream -> d_out stream0, sin/cos split
    sincos_kernel<<<VG4, EW>>>(out);

    // connectivity: [sin;cos] [2048,512] x lambda_b^T -> partials in g_SSp
    hmma_gemm<<<dim3(NB / 64, 2 * BATCH / 128, 2), 256, GSM>>>(pSCh, pSCl, pLb, pSSp, 2 * BATCH, NB, NB, nullptr, 0);

    // combine streams 1,2 + physics -> d_out
    final_kernel<<<VG4, EW>>>(out, lm, ld, p);
}